// round 16
// baseline (speedup 1.0000x reference)
#include <cuda_runtime.h>
#include <cuda_bf16.h>
#include <math.h>
#include <stdint.h>

// Problem constants
#define BB 2
#define SS 2048
#define HH 2048
#define NH 16
#define HD 128
#define SCALE 0.08838834764831845f  // 1/sqrt(128)

#define NTOK (BB * SS)                        // 4096
#define HSN  ((size_t)NTOK * HH)              // 8.39M
#define WN   ((size_t)HH * HH)                // 4.19M
#define QKVN ((size_t)BB * NH * SS * HD)      // 8.39M

// ---------------- scratch (device globals; no allocation allowed) ----------
__device__ float g_q[QKVN];
__device__ float g_k[QKVN];
__device__ float g_v[QKVN];
__device__ __nv_bfloat16 g_hsH[HSN], g_hsL[HSN];
__device__ __nv_bfloat16 g_wqH[WN], g_wqL[WN];
__device__ __nv_bfloat16 g_wkH[WN], g_wkL[WN];
__device__ __nv_bfloat16 g_wvH[WN], g_wvL[WN];
__device__ __nv_bfloat16 g_woH[WN], g_woL[WN];
__device__ __nv_bfloat16 g_qH[QKVN], g_qL[QKVN];
__device__ __nv_bfloat16 g_kH[QKVN], g_kL[QKVN];
__device__ __nv_bfloat16 g_vH[QKVN], g_vL[QKVN];
__device__ __nv_bfloat16 g_attH[HSN], g_attL[HSN];

// ---------------- bf16 split + mma helpers (HW-validated R15) --------------
__device__ __forceinline__ void split_bf16x2(float f0, float f1,
                                             uint32_t& h, uint32_t& l) {
    uint32_t hp;
    asm("cvt.rn.bf16x2.f32 %0, %1, %2;" : "=r"(hp) : "f"(f1), "f"(f0));
    float h0 = __uint_as_float(hp << 16);
    float h1 = __uint_as_float(hp & 0xFFFF0000u);
    asm("cvt.rn.bf16x2.f32 %0, %1, %2;" : "=r"(l) : "f"(f1 - h1), "f"(f0 - h0));
    h = hp;
}

__device__ __forceinline__ void mma_bf16(float* c,
                                         const uint32_t* a,
                                         const uint32_t* b) {
    asm volatile(
        "mma.sync.aligned.m16n8k16.row.col.f32.bf16.bf16.f32 "
        "{%0,%1,%2,%3}, {%4,%5,%6,%7}, {%8,%9}, {%0,%1,%2,%3};"
        : "+f"(c[0]), "+f"(c[1]), "+f"(c[2]), "+f"(c[3])
        : "r"(a[0]), "r"(a[1]), "r"(a[2]), "r"(a[3]),
          "r"(b[0]), "r"(b[1]));
}

// ---------------- converter: f32 -> (bf16 hi, bf16 lo) ---------------------
__global__ void __launch_bounds__(256) convert_split(
    const float* __restrict__ s, __nv_bfloat16* __restrict__ dh,
    __nv_bfloat16* __restrict__ dl, int n4) {
    int i = blockIdx.x * blockDim.x + threadIdx.x;
    if (i >= n4) return;
    float4 f = ((const float4*)s)[i];
    uint32_t h0, l0, h1, l1;
    split_bf16x2(f.x, f.y, h0, l0);
    split_bf16x2(f.z, f.w, h1, l1);
    ((uint2*)dh)[i] = make_uint2(h0, h1);
    ((uint2*)dl)[i] = make_uint2(l0, l1);
}

// ---------------- bf16-split GEMM (pre-split GMEM inputs) ------------------
// C[m,n] = sum_k A[m,k]*W[n,k] (NT). BM=BN=128, BK=16, 256 thr, 8 warps 2x4.
// Smem: [2 buf][4 arr: AH,AL,WH,WL][128 rows][24 bf16 pitch] = 49152 B.
// Fragment bank = (12g+tg) mod 32: all 32 distinct -> conflict-free.
#define GBK 16
#define GROWB 48                 // 24 bf16 * 2B row pitch (bytes)
#define GARRB (128 * GROWB)      // bytes per array
#define GEMM_SMEM_B (2 * 4 * GARRB)  // 49152

template <int MODE>
__device__ __forceinline__ void gemm_bf16_body(
    const __nv_bfloat16* __restrict__ AH, const __nv_bfloat16* __restrict__ AL,
    const __nv_bfloat16* __restrict__ WH, const __nv_bfloat16* __restrict__ WL,
    float* __restrict__ C, int K, int N) {
    extern __shared__ char gs[];

    const int bn = blockIdx.x;
    const int bm = blockIdx.y;
    const int t  = threadIdx.x;
    const int wid  = t >> 5;
    const int lane = t & 31;
    const int g  = lane >> 2;
    const int tg = lane & 3;
    const int wm = (wid & 1) * 64;
    const int wn = (wid >> 1) * 32;

    const __nv_bfloat16* srcs[4] = {
        AH + (size_t)(bm * 128) * K, AL + (size_t)(bm * 128) * K,
        WH + (size_t)(bn * 128) * K, WL + (size_t)(bn * 128) * K };

    float acc[4][4][4];
#pragma unroll
    for (int i = 0; i < 4; i++)
#pragma unroll
        for (int j = 0; j < 4; j++)
#pragma unroll
            for (int r = 0; r < 4; r++) acc[i][j][r] = 0.f;

    // prologue: stage K-tile 0 into buffer 0 (4 uint4 tasks per thread)
#pragma unroll
    for (int it = 0; it < 4; it++) {
        int task = t + it * 256;
        int arr = task >> 8, row = (task >> 1) & 127, half = task & 1;
        uint4 v = *(const uint4*)(srcs[arr] + (size_t)row * K + half * 8);
        *(uint4*)(gs + arr * GARRB + row * GROWB + half * 16) = v;
    }
    __syncthreads();

    int buf = 0;
    for (int kt = 0; kt < K; kt += GBK) {
        const bool has_next = (kt + GBK) < K;
        uint4 pf[4];
        if (has_next) {
#pragma unroll
            for (int it = 0; it < 4; it++) {
                int task = t + it * 256;
                int arr = task >> 8, row = (task >> 1) & 127, half = task & 1;
                pf[it] = *(const uint4*)(srcs[arr] + (size_t)row * K +
                                         kt + GBK + half * 8);
            }
        }

        const char* base = gs + buf * 4 * GARRB;
        uint32_t Ah[4][4], Al[4][4], Bh[4][2], Bl[4][2];
#pragma unroll
        for (int i = 0; i < 4; i++) {
            int row = wm + i * 16 + g;
            const char* pH = base + 0 * GARRB + row * GROWB + 4 * tg;
            const char* pL = base + 1 * GARRB + row * GROWB + 4 * tg;
            Ah[i][0] = *(const uint32_t*)(pH);
            Ah[i][1] = *(const uint32_t*)(pH + 8 * GROWB);
            Ah[i][2] = *(const uint32_t*)(pH + 16);
            Ah[i][3] = *(const uint32_t*)(pH + 8 * GROWB + 16);
            Al[i][0] = *(const uint32_t*)(pL);
            Al[i][1] = *(const uint32_t*)(pL + 8 * GROWB);
            Al[i][2] = *(const uint32_t*)(pL + 16);
            Al[i][3] = *(const uint32_t*)(pL + 8 * GROWB + 16);
        }
#pragma unroll
        for (int j = 0; j < 4; j++) {
            int col = wn + j * 8 + g;
            const char* pH = base + 2 * GARRB + col * GROWB + 4 * tg;
            const char* pL = base + 3 * GARRB + col * GROWB + 4 * tg;
            Bh[j][0] = *(const uint32_t*)(pH);
            Bh[j][1] = *(const uint32_t*)(pH + 16);
            Bl[j][0] = *(const uint32_t*)(pL);
            Bl[j][1] = *(const uint32_t*)(pL + 16);
        }

        // term-major passes (no back-to-back RAW on one accumulator)
#pragma unroll
        for (int i = 0; i < 4; i++)
#pragma unroll
            for (int j = 0; j < 4; j++) mma_bf16(acc[i][j], Ah[i], Bh[j]);
#pragma unroll
        for (int i = 0; i < 4; i++)
#pragma unroll
            for (int j = 0; j < 4; j++) mma_bf16(acc[i][j], Ah[i], Bl[j]);
#pragma unroll
        for (int i = 0; i < 4; i++)
#pragma unroll
            for (int j = 0; j < 4; j++) mma_bf16(acc[i][j], Al[i], Bh[j]);

        if (has_next) {
            char* nb = gs + (buf ^ 1) * 4 * GARRB;
#pragma unroll
            for (int it = 0; it < 4; it++) {
                int task = t + it * 256;
                int arr = task >> 8, row = (task >> 1) & 127, half = task & 1;
                *(uint4*)(nb + arr * GARRB + row * GROWB + half * 16) = pf[it];
            }
            __syncthreads();
        }
        buf ^= 1;
    }

#pragma unroll
    for (int i = 0; i < 4; i++) {
#pragma unroll
        for (int j = 0; j < 4; j++) {
            int m0 = bm * 128 + wm + i * 16 + g;
            int n0 = bn * 128 + wn + j * 8 + tg * 2;
#pragma unroll
            for (int r = 0; r < 4; r++) {
                int m = m0 + (r >> 1) * 8;
                int n = n0 + (r & 1);
                if (MODE == 0) {
                    int b  = m >> 11;
                    int s  = m & (SS - 1);
                    int nh = n >> 7;
                    int hd = n & (HD - 1);
                    size_t o = ((((size_t)b * NH + nh) << 11) + s) * HD + hd;
                    C[o] = acc[i][j][r];
                } else {
                    C[(size_t)m * N + n] = acc[i][j][r];
                }
            }
        }
    }
}

__global__ void __launch_bounds__(256, 2) sgemm_qkv(
    const __nv_bfloat16* __restrict__ AH, const __nv_bfloat16* __restrict__ AL,
    const __nv_bfloat16* __restrict__ WqH, const __nv_bfloat16* __restrict__ WqL,
    const __nv_bfloat16* __restrict__ WkH, const __nv_bfloat16* __restrict__ WkL,
    const __nv_bfloat16* __restrict__ WvH, const __nv_bfloat16* __restrict__ WvL,
    float* __restrict__ q, float* __restrict__ k, float* __restrict__ v) {
    const __nv_bfloat16* WH = (blockIdx.z == 0) ? WqH : (blockIdx.z == 1) ? WkH : WvH;
    const __nv_bfloat16* WL = (blockIdx.z == 0) ? WqL : (blockIdx.z == 1) ? WkL : WvL;
    float* C = (blockIdx.z == 0) ? q : (blockIdx.z == 1) ? k : v;
    gemm_bf16_body<0>(AH, AL, WH, WL, C, HH, HH);
}

__global__ void __launch_bounds__(256, 2) sgemm_out(
    const __nv_bfloat16* __restrict__ AH, const __nv_bfloat16* __restrict__ AL,
    const __nv_bfloat16* __restrict__ WH, const __nv_bfloat16* __restrict__ WL,
    float* __restrict__ C) {
    gemm_bf16_body<1>(AH, AL, WH, WL, C, HH, HH);
}

// ---------------- RoPE: read f32 q/k, write rotated hi/lo bf16 -------------
__global__ void __launch_bounds__(256) rope_split_kernel(
    const float* __restrict__ q, const float* __restrict__ k,
    const float* __restrict__ cosp, const float* __restrict__ sinp,
    __nv_bfloat16* __restrict__ qh, __nv_bfloat16* __restrict__ ql,
    __nv_bfloat16* __restrict__ kh, __nv_bfloat16* __restrict__ kl) {
    const int total = BB * NH * SS * (HD / 2);
    int idx = blockIdx.x * blockDim.x + threadIdx.x;
    const float* sp = q;
    __nv_bfloat16 *dh = qh, *dl = ql;
    if (idx >= total) { idx -= total; sp = k; dh = kh; dl = kl; }
    if (idx >= total) return;

    int hd = idx & 63;
    int ro = idx >> 6;
    int s  = ro & (SS - 1);
    size_t base = (size_t)ro * HD;

    float x1 = sp[base + hd];
    float x2 = sp[base + hd + 64];
    float c1 = cosp[s * HD + hd];
    float s1 = sinp[s * HD + hd];
    float c2 = cosp[s * HD + hd + 64];
    float s2 = sinp[s * HD + hd + 64];
    float y1 = x1 * c1 - x2 * s1;
    float y2 = x2 * c2 + x1 * s2;

    __nv_bfloat16 h1 = __float2bfloat16(y1);
    __nv_bfloat16 h2 = __float2bfloat16(y2);
    dh[base + hd]      = h1;
    dl[base + hd]      = __float2bfloat16(y1 - __bfloat162float(h1));
    dh[base + hd + 64] = h2;
    dl[base + hd + 64] = __float2bfloat16(y2 - __bfloat162float(h2));
}

// ---------------- Tensorized flash (pre-split bf16 Q/K/V) ------------------
#define BQF 128
#define BKF 64
#define FQP 136     // bf16 pitch for Q/K rows (272 B, conflict-free)
#define FVP 72      // bf16 pitch for Vt rows  (144 B, conflict-free)
#define FPP 68      // f32 pitch for Ps
#define F_QH 0
#define F_QL (F_QH + BQF * FQP)
#define F_KH (F_QL + BQF * FQP)
#define F_KL (F_KH + BKF * FQP)
#define F_VH (F_KL + BKF * FQP)
#define F_VL (F_VH + HD * FVP)
#define F_END (F_VL + HD * FVP)                 // bf16 units
#define FLASH3_SMEM (F_END * 2 + BQF * FPP * 4) // 176128 B

__global__ void __launch_bounds__(256, 1) flash_mma_kernel(
    const __nv_bfloat16* __restrict__ qh, const __nv_bfloat16* __restrict__ ql,
    const __nv_bfloat16* __restrict__ kh, const __nv_bfloat16* __restrict__ kl,
    const __nv_bfloat16* __restrict__ vh, const __nv_bfloat16* __restrict__ vl,
    __nv_bfloat16* __restrict__ oh, __nv_bfloat16* __restrict__ ol) {
    extern __shared__ char fsc[];
    __nv_bfloat16* fsb = (__nv_bfloat16*)fsc;
    float* Ps = (float*)(fsc + F_END * 2);

    const int qt = (SS / BQF - 1) - blockIdx.x;   // heavy tiles first
    const int nh = blockIdx.y;
    const int b  = blockIdx.z;
    const int bh = b * NH + nh;
    const __nv_bfloat16* qhb = qh + (size_t)bh * SS * HD;
    const __nv_bfloat16* qlb = ql + (size_t)bh * SS * HD;
    const __nv_bfloat16* khb = kh + (size_t)bh * SS * HD;
    const __nv_bfloat16* klb = kl + (size_t)bh * SS * HD;
    const __nv_bfloat16* vhb = vh + (size_t)bh * SS * HD;
    const __nv_bfloat16* vlb = vl + (size_t)bh * SS * HD;

    const int tid  = threadIdx.x;
    const int wid  = tid >> 5;
    const int lane = tid & 31;
    const int g  = lane >> 2;
    const int tg = lane & 3;
    const int r0 = wid * 16 + g;
    const int qg0 = qt * BQF + r0;
    const int qg1 = qg0 + 8;

    // stage Q tile (bf16 hi/lo): 128 rows x 16 uint4-cols x 2 arrays
    for (int it = tid; it < BQF * 16 * 2; it += 256) {
        int arr = it >> 11;
        int row = (it >> 4) & 127;
        int c8  = it & 15;
        const __nv_bfloat16* src =
            (arr ? qlb : qhb) + (size_t)(qt * BQF + row) * HD + c8 * 8;
        __nv_bfloat16* dst = fsb + (arr ? F_QL : F_QH) + row * FQP + c8 * 8;
        *(uint4*)dst = *(const uint4*)src;
    }

    float o[16][4];
#pragma unroll
    for (int j = 0; j < 16; j++)
#pragma unroll
        for (int r = 0; r < 4; r++) o[j][r] = 0.f;
    float m0 = -INFINITY, m1 = -INFINITY, l0 = 0.f, l1 = 0.f;

    const int nkt = 2 * qt + 2;
    for (int kt = 0; kt < nkt; ++kt) {
        __syncthreads();
        // K tiles: 64 rows x 16 uint4-cols x 2 arrays
        for (int it = tid; it < BKF * 16 * 2; it += 256) {
            int arr = it >> 10;
            int row = (it >> 4) & 63;
            int c8  = it & 15;
            const __nv_bfloat16* src =
                (arr ? klb : khb) + (size_t)(kt * BKF + row) * HD + c8 * 8;
            __nv_bfloat16* dst = fsb + (arr ? F_KL : F_KH) + row * FQP + c8 * 8;
            *(uint4*)dst = *(const uint4*)src;
        }
        // V tiles (transposed): same task shape, scatter 8 bf16 per uint4
        for (int it = tid; it < BKF * 16 * 2; it += 256) {
            int arr = it >> 10;
            int row = (it >> 4) & 63;
            int c8  = it & 15;
            const __nv_bfloat16* src =
                (arr ? vlb : vhb) + (size_t)(kt * BKF + row) * HD + c8 * 8;
            uint4 v = *(const uint4*)src;
            const __nv_bfloat16* ev = (const __nv_bfloat16*)&v;
            __nv_bfloat16* dstb = fsb + (arr ? F_VL : F_VH);
#pragma unroll
            for (int e = 0; e < 8; e++)
                dstb[(c8 * 8 + e) * FVP + row] = ev[e];
        }
        __syncthreads();

        // ---- S = Q K^T (m16n8k16 chunks, pure LDS+MMA) ----
        float s[8][4];
#pragma unroll
        for (int j = 0; j < 8; j++)
#pragma unroll
            for (int r = 0; r < 4; r++) s[j][r] = 0.f;

        for (int k0 = 0; k0 < HD; k0 += 16) {
            uint32_t Ah[4], Al[4];
            const __nv_bfloat16* qH0 = fsb + F_QH + r0 * FQP + k0 + 2 * tg;
            const __nv_bfloat16* qL0 = fsb + F_QL + r0 * FQP + k0 + 2 * tg;
            Ah[0] = *(const uint32_t*)(qH0);
            Ah[1] = *(const uint32_t*)(qH0 + 8 * FQP);
            Ah[2] = *(const uint32_t*)(qH0 + 8);
            Ah[3] = *(const uint32_t*)(qH0 + 8 * FQP + 8);
            Al[0] = *(const uint32_t*)(qL0);
            Al[1] = *(const uint32_t*)(qL0 + 8 * FQP);
            Al[2] = *(const uint32_t*)(qL0 + 8);
            Al[3] = *(const uint32_t*)(qL0 + 8 * FQP + 8);
#pragma unroll
            for (int nj = 0; nj < 8; nj++) {
                uint32_t Bh[2], Bl[2];
                const __nv_bfloat16* kH0 =
                    fsb + F_KH + (nj * 8 + g) * FQP + k0 + 2 * tg;
                const __nv_bfloat16* kL0 =
                    fsb + F_KL + (nj * 8 + g) * FQP + k0 + 2 * tg;
                Bh[0] = *(const uint32_t*)(kH0);
                Bh[1] = *(const uint32_t*)(kH0 + 8);
                Bl[0] = *(const uint32_t*)(kL0);
                Bl[1] = *(const uint32_t*)(kL0 + 8);
                mma_bf16(s[nj], Ah, Bh);
                mma_bf16(s[nj], Ah, Bl);
                mma_bf16(s[nj], Al, Bh);
            }
        }

        // ---- online softmax (unchanged, validated) ----
        const int colbase = kt * BKF + tg * 2;
        float rm0 = -INFINITY, rm1 = -INFINITY;
#pragma unroll
        for (int nj = 0; nj < 8; nj++) {
#pragma unroll
            for (int e = 0; e < 2; e++) {
                int c = colbase + nj * 8 + e;
                float v0 = s[nj][e] * SCALE;
                if (c > qg0) v0 = -INFINITY;
                s[nj][e] = v0;
                rm0 = fmaxf(rm0, v0);
                float v1 = s[nj][2 + e] * SCALE;
                if (c > qg1) v1 = -INFINITY;
                s[nj][2 + e] = v1;
                rm1 = fmaxf(rm1, v1);
            }
        }
        rm0 = fmaxf(rm0, __shfl_xor_sync(0xffffffffu, rm0, 1));
        rm0 = fmaxf(rm0, __shfl_xor_sync(0xffffffffu, rm0, 2));
        rm1 = fmaxf(rm1, __shfl_xor_sync(0xffffffffu, rm1, 1));
        rm1 = fmaxf(rm1, __shfl_xor_sync(0xffffffffu, rm1, 2));

        float mn0 = fmaxf(m0, rm0), mn1 = fmaxf(m1, rm1);
        float cr0 = __expf(m0 - mn0), cr1 = __expf(m1 - mn1);
        float rs0 = 0.f, rs1 = 0.f;
#pragma unroll
        for (int nj = 0; nj < 8; nj++) {
            float p0 = __expf(s[nj][0] - mn0);
            float p1 = __expf(s[nj][1] - mn0);
            float p2 = __expf(s[nj][2] - mn1);
            float p3 = __expf(s[nj][3] - mn1);
            rs0 += p0 + p1;
            rs1 += p2 + p3;
            *(float2*)&Ps[r0 * FPP + nj * 8 + 2 * tg]       = make_float2(p0, p1);
            *(float2*)&Ps[(r0 + 8) * FPP + nj * 8 + 2 * tg] = make_float2(p2, p3);
        }
        rs0 += __shfl_xor_sync(0xffffffffu, rs0, 1);
        rs0 += __shfl_xor_sync(0xffffffffu, rs0, 2);
        rs1 += __shfl_xor_sync(0xffffffffu, rs1, 1);
        rs1 += __shfl_xor_sync(0xffffffffu, rs1, 2);
        l0 = l0 * cr0 + rs0;
        l1 = l1 * cr1 + rs1;
        m0 = mn0; m1 = mn1;
#pragma unroll
        for (int j = 0; j < 16; j++) {
            o[j][0] *= cr0; o[j][1] *= cr0;
            o[j][2] *= cr1; o[j][3] *= cr1;
        }
        __syncwarp();   // Ps rows warp-private; publish cross-lane writes

        // ---- O += P V (P split on the fly; V pre-split) ----
        for (int k0 = 0; k0 < BKF; k0 += 16) {
            uint32_t Ah[4], Al[4];
            float2 fa;
            fa = *(const float2*)&Ps[r0 * FPP + k0 + 2 * tg];
            split_bf16x2(fa.x, fa.y, Ah[0], Al[0]);
            fa = *(const float2*)&Ps[(r0 + 8) * FPP + k0 + 2 * tg];
            split_bf16x2(fa.x, fa.y, Ah[1], Al[1]);
            fa = *(const float2*)&Ps[r0 * FPP + k0 + 2 * tg + 8];
            split_bf16x2(fa.x, fa.y, Ah[2], Al[2]);
            fa = *(const float2*)&Ps[(r0 + 8) * FPP + k0 + 2 * tg + 8];
            split_bf16x2(fa.x, fa.y, Ah[3], Al[3]);
#pragma unroll
            for (int nj = 0; nj < 16; nj++) {
                uint32_t Bh[2], Bl[2];
                const __nv_bfloat16* vH0 =
                    fsb + F_VH + (nj * 8 + g) * FVP + k0 + 2 * tg;
                const __nv_bfloat16* vL0 =
                    fsb + F_VL + (nj * 8 + g) * FVP + k0 + 2 * tg;
                Bh[0] = *(const uint32_t*)(vH0);
                Bh[1] = *(const uint32_t*)(vH0 + 8);
                Bl[0] = *(const uint32_t*)(vL0);
                Bl[1] = *(const uint32_t*)(vL0 + 8);
                mma_bf16(o[nj], Ah, Bh);
                mma_bf16(o[nj], Ah, Bl);
                mma_bf16(o[nj], Al, Bh);
            }
        }
    }

    // ---- normalize + write att as bf16 hi/lo pairs ----
    float il0 = 1.0f / l0, il1 = 1.0f / l1;
    size_t ob0 = ((size_t)(b * SS + qg0)) * HH + nh * HD;
    size_t ob1 = ((size_t)(b * SS + qg1)) * HH + nh * HD;
#pragma unroll
    for (int nj = 0; nj < 16; nj++) {
        uint32_t h, l;
        split_bf16x2(o[nj][0] * il0, o[nj][1] * il0, h, l);
        *(uint32_t*)(oh + ob0 + nj * 8 + 2 * tg) = h;
        *(uint32_t*)(ol + ob0 + nj * 8 + 2 * tg) = l;
        split_bf16x2(o[nj][2] * il1, o[nj][3] * il1, h, l);
        *(uint32_t*)(oh + ob1 + nj * 8 + 2 * tg) = h;
        *(uint32_t*)(ol + ob1 + nj * 8 + 2 * tg) = l;
    }
}

// ---------------- launch ---------------------------------------------------
extern "C" void kernel_launch(void* const* d_in, const int* in_sizes, int n_in,
                              void* d_out, int out_size) {
    const float* hs   = (const float*)d_in[0];
    const float* cosp = (const float*)d_in[1];
    const float* sinp = (const float*)d_in[2];
    const float* Wq   = (const float*)d_in[3];
    const float* Wk   = (const float*)d_in[4];
    const float* Wv   = (const float*)d_in[5];
    const float* Wo   = (const float*)d_in[6];
    float* out = (float*)d_out;

    float *qp, *kp, *vp;
    cudaGetSymbolAddress((void**)&qp, g_q);
    cudaGetSymbolAddress((void**)&kp, g_k);
    cudaGetSymbolAddress((void**)&vp, g_v);
    __nv_bfloat16 *hsH, *hsL, *wqH, *wqL, *wkH, *wkL, *wvH, *wvL, *woH, *woL;
    __nv_bfloat16 *qH, *qL, *kH, *kL, *vH, *vL, *attH, *attL;
    cudaGetSymbolAddress((void**)&hsH, g_hsH);
    cudaGetSymbolAddress((void**)&hsL, g_hsL);
    cudaGetSymbolAddress((void**)&wqH, g_wqH);
    cudaGetSymbolAddress((void**)&wqL, g_wqL);
    cudaGetSymbolAddress((void**)&wkH, g_wkH);
    cudaGetSymbolAddress((void**)&wkL, g_wkL);
    cudaGetSymbolAddress((void**)&wvH, g_wvH);
    cudaGetSymbolAddress((void**)&wvL, g_wvL);
    cudaGetSymbolAddress((void**)&woH, g_woH);
    cudaGetSymbolAddress((void**)&woL, g_woL);
    cudaGetSymbolAddress((void**)&qH, g_qH);
    cudaGetSymbolAddress((void**)&qL, g_qL);
    cudaGetSymbolAddress((void**)&kH, g_kH);
    cudaGetSymbolAddress((void**)&kL, g_kL);
    cudaGetSymbolAddress((void**)&vH, g_vH);
    cudaGetSymbolAddress((void**)&vL, g_vL);
    cudaGetSymbolAddress((void**)&attH, g_attH);
    cudaGetSymbolAddress((void**)&attL, g_attL);

    cudaFuncSetAttribute(sgemm_qkv,
                         cudaFuncAttributeMaxDynamicSharedMemorySize, GEMM_SMEM_B);
    cudaFuncSetAttribute(sgemm_out,
                         cudaFuncAttributeMaxDynamicSharedMemorySize, GEMM_SMEM_B);
    cudaFuncSetAttribute(flash_mma_kernel,
                         cudaFuncAttributeMaxDynamicSharedMemorySize, FLASH3_SMEM);

    // 0) pre-split inputs to bf16 hi/lo
    int hs4 = (int)(HSN / 4), w4 = (int)(WN / 4), qkv4 = (int)(QKVN / 4);
    convert_split<<<(hs4 + 255) / 256, 256>>>(hs, hsH, hsL, hs4);
    convert_split<<<(w4 + 255) / 256, 256>>>(Wq, wqH, wqL, w4);
    convert_split<<<(w4 + 255) / 256, 256>>>(Wk, wkH, wkL, w4);
    convert_split<<<(w4 + 255) / 256, 256>>>(Wv, wvH, wvL, w4);
    convert_split<<<(w4 + 255) / 256, 256>>>(Wo, woH, woL, w4);

    // 1) QKV projections
    dim3 pg(HH / 128, NTOK / 128, 3);
    sgemm_qkv<<<pg, 256, GEMM_SMEM_B>>>(hsH, hsL, wqH, wqL, wkH, wkL,
                                        wvH, wvL, qp, kp, vp);

    // 2) RoPE -> bf16 hi/lo q,k ; convert v
    int pairs = 2 * BB * NH * SS * (HD / 2);
    rope_split_kernel<<<(pairs + 255) / 256, 256>>>(qp, kp, cosp, sinp,
                                                    qH, qL, kH, kL);
    convert_split<<<(qkv4 + 255) / 256, 256>>>(vp, vH, vL, qkv4);

    // 3) causal flash attention (bf16 in, bf16 att out)
    dim3 fg(SS / BQF, NH, BB);
    flash_mma_kernel<<<fg, 256, FLASH3_SMEM>>>(qH, qL, kH, kL, vH, vL,
                                               attH, attL);

    // 4) output projection
    dim3 og(HH / 128, NTOK / 128, 1);
    sgemm_out<<<og, 256, GEMM_SMEM_B>>>(attH, attL, woH, woL, out);
}

// round 17
// speedup vs baseline: 1.1916x; 1.1916x over previous
#include <cuda_runtime.h>
#include <math.h>
#include <stdint.h>

// Problem constants
#define BB 2
#define SS 2048
#define HH 2048
#define NH 16
#define HD 128
#define SCALE 0.08838834764831845f  // 1/sqrt(128)

// ---------------- scratch (device globals; no allocation allowed) ----------
__device__ float g_q[(size_t)BB * NH * SS * HD];
__device__ float g_k[(size_t)BB * NH * SS * HD];
__device__ float g_v[(size_t)BB * NH * SS * HD];
__device__ float g_att[(size_t)BB * SS * HH];

// ---------------- bf16 split + mma helpers (HW-validated R15) --------------
__device__ __forceinline__ void split_bf16x2(float f0, float f1,
                                             uint32_t& h, uint32_t& l) {
    uint32_t hp;
    asm("cvt.rn.bf16x2.f32 %0, %1, %2;" : "=r"(hp) : "f"(f1), "f"(f0));
    float h0 = __uint_as_float(hp << 16);
    float h1 = __uint_as_float(hp & 0xFFFF0000u);
    asm("cvt.rn.bf16x2.f32 %0, %1, %2;" : "=r"(l) : "f"(f1 - h1), "f"(f0 - h0));
    h = hp;
}

__device__ __forceinline__ void mma_bf16(float* c,
                                         const uint32_t* a,
                                         const uint32_t* b) {
    asm volatile(
        "mma.sync.aligned.m16n8k16.row.col.f32.bf16.bf16.f32 "
        "{%0,%1,%2,%3}, {%4,%5,%6,%7}, {%8,%9}, {%0,%1,%2,%3};"
        : "+f"(c[0]), "+f"(c[1]), "+f"(c[2]), "+f"(c[3])
        : "r"(a[0]), "r"(a[1]), "r"(a[2]), "r"(a[3]),
          "r"(b[0]), "r"(b[1]));
}

// split 4 consecutive f32 -> bf16 hi/lo uint2 pairs, store to smem
__device__ __forceinline__ void split_store4b(char* dH, char* dL, float4 f) {
    uint32_t h0, l0, h1, l1;
    split_bf16x2(f.x, f.y, h0, l0);
    split_bf16x2(f.z, f.w, h1, l1);
    *(uint2*)dH = make_uint2(h0, h1);
    *(uint2*)dL = make_uint2(l0, l1);
}

// ---------------- bf16-split GEMM: split at staging into bf16 smem ---------
// C[m,n] = sum_k A[m,k]*W[n,k] (NT). BM=BN=128, BK=16, 256 thr, 8 warps 2x4.
// Smem per buffer: AH,AL,WH,WL bf16[128][24] (48 B rows). Hot loop: pure
// LDS.32 + MMA (split values bit-identical to R15's on-the-fly split).
// Fragment bank = (12g+tg) mod 32: all 32 distinct -> conflict-free.
#define GBK 16
#define GROWB 48                     // bytes per row (24 bf16)
#define GARRB (128 * GROWB)          // 6144 B per array
#define GBUFB (4 * GARRB)            // 24576 B per buffer
#define GEMM_SMEM_B (2 * GBUFB)      // 49152 B

template <int MODE>
__device__ __forceinline__ void gemm_bf16_body(const float* __restrict__ A,
                                               const float* __restrict__ W,
                                               float* __restrict__ C,
                                               int K, int N) {
    extern __shared__ char gs[];

    const int bn = blockIdx.x;
    const int bm = blockIdx.y;
    const int t  = threadIdx.x;
    const int wid  = t >> 5;
    const int lane = t & 31;
    const int g  = lane >> 2;
    const int tg = lane & 3;
    const int wm = (wid & 1) * 64;
    const int wn = (wid >> 1) * 32;

    const float* Ablk = A + (size_t)(bm * 128) * K;
    const float* Wblk = W + (size_t)(bn * 128) * K;

    const int r0 = t >> 2;           // 0..63
    const int q0 = (t & 3) * 4;      // 0,4,8,12 (floats)
    const int r1 = r0 + 64;          // 64..127

    float acc[4][4][4];
#pragma unroll
    for (int i = 0; i < 4; i++)
#pragma unroll
        for (int j = 0; j < 4; j++)
#pragma unroll
            for (int r = 0; r < 4; r++) acc[i][j][r] = 0.f;

    // prologue: stage K-tile 0 into buffer 0 (split to bf16 at staging)
    {
        char* b0 = gs;
        split_store4b(b0 + 0 * GARRB + r0 * GROWB + 2 * q0,
                      b0 + 1 * GARRB + r0 * GROWB + 2 * q0,
                      *(const float4*)(Ablk + (size_t)r0 * K + q0));
        split_store4b(b0 + 0 * GARRB + r1 * GROWB + 2 * q0,
                      b0 + 1 * GARRB + r1 * GROWB + 2 * q0,
                      *(const float4*)(Ablk + (size_t)r1 * K + q0));
        split_store4b(b0 + 2 * GARRB + r0 * GROWB + 2 * q0,
                      b0 + 3 * GARRB + r0 * GROWB + 2 * q0,
                      *(const float4*)(Wblk + (size_t)r0 * K + q0));
        split_store4b(b0 + 2 * GARRB + r1 * GROWB + 2 * q0,
                      b0 + 3 * GARRB + r1 * GROWB + 2 * q0,
                      *(const float4*)(Wblk + (size_t)r1 * K + q0));
    }
    __syncthreads();

    int buf = 0;
    for (int kt = 0; kt < K; kt += GBK) {
        const bool has_next = (kt + GBK) < K;
        float4 pa0, pa1, pw0, pw1;
        if (has_next) {
            pa0 = *(const float4*)(Ablk + (size_t)r0 * K + kt + GBK + q0);
            pa1 = *(const float4*)(Ablk + (size_t)r1 * K + kt + GBK + q0);
            pw0 = *(const float4*)(Wblk + (size_t)r0 * K + kt + GBK + q0);
            pw1 = *(const float4*)(Wblk + (size_t)r1 * K + kt + GBK + q0);
        }

        const char* base = gs + buf * GBUFB;
        uint32_t Ah[4][4], Al[4][4], Bh[4][2], Bl[4][2];
#pragma unroll
        for (int i = 0; i < 4; i++) {
            int row = wm + i * 16 + g;
            const char* pH = base + 0 * GARRB + row * GROWB + 4 * tg;
            const char* pL = base + 1 * GARRB + row * GROWB + 4 * tg;
            Ah[i][0] = *(const uint32_t*)(pH);
            Ah[i][1] = *(const uint32_t*)(pH + 8 * GROWB);
            Ah[i][2] = *(const uint32_t*)(pH + 16);
            Ah[i][3] = *(const uint32_t*)(pH + 8 * GROWB + 16);
            Al[i][0] = *(const uint32_t*)(pL);
            Al[i][1] = *(const uint32_t*)(pL + 8 * GROWB);
            Al[i][2] = *(const uint32_t*)(pL + 16);
            Al[i][3] = *(const uint32_t*)(pL + 8 * GROWB + 16);
        }
#pragma unroll
        for (int j = 0; j < 4; j++) {
            int col = wn + j * 8 + g;
            const char* pH = base + 2 * GARRB + col * GROWB + 4 * tg;
            const char* pL = base + 3 * GARRB + col * GROWB + 4 * tg;
            Bh[j][0] = *(const uint32_t*)(pH);
            Bh[j][1] = *(const uint32_t*)(pH + 16);
            Bl[j][0] = *(const uint32_t*)(pL);
            Bl[j][1] = *(const uint32_t*)(pL + 16);
        }

        // term-major passes (no back-to-back RAW on one accumulator)
#pragma unroll
        for (int i = 0; i < 4; i++)
#pragma unroll
            for (int j = 0; j < 4; j++) mma_bf16(acc[i][j], Ah[i], Bh[j]);
#pragma unroll
        for (int i = 0; i < 4; i++)
#pragma unroll
            for (int j = 0; j < 4; j++) mma_bf16(acc[i][j], Ah[i], Bl[j]);
#pragma unroll
        for (int i = 0; i < 4; i++)
#pragma unroll
            for (int j = 0; j < 4; j++) mma_bf16(acc[i][j], Al[i], Bh[j]);

        if (has_next) {
            char* nb = gs + (buf ^ 1) * GBUFB;
            split_store4b(nb + 0 * GARRB + r0 * GROWB + 2 * q0,
                          nb + 1 * GARRB + r0 * GROWB + 2 * q0, pa0);
            split_store4b(nb + 0 * GARRB + r1 * GROWB + 2 * q0,
                          nb + 1 * GARRB + r1 * GROWB + 2 * q0, pa1);
            split_store4b(nb + 2 * GARRB + r0 * GROWB + 2 * q0,
                          nb + 3 * GARRB + r0 * GROWB + 2 * q0, pw0);
            split_store4b(nb + 2 * GARRB + r1 * GROWB + 2 * q0,
                          nb + 3 * GARRB + r1 * GROWB + 2 * q0, pw1);
            __syncthreads();
        }
        buf ^= 1;
    }

#pragma unroll
    for (int i = 0; i < 4; i++) {
#pragma unroll
        for (int j = 0; j < 4; j++) {
            int m0 = bm * 128 + wm + i * 16 + g;
            int n0 = bn * 128 + wn + j * 8 + tg * 2;
#pragma unroll
            for (int r = 0; r < 4; r++) {
                int m = m0 + (r >> 1) * 8;
                int n = n0 + (r & 1);
                if (MODE == 0) {
                    int b  = m >> 11;
                    int s  = m & (SS - 1);
                    int nh = n >> 7;
                    int hd = n & (HD - 1);
                    size_t o = ((((size_t)b * NH + nh) << 11) + s) * HD + hd;
                    C[o] = acc[i][j][r];
                } else {
                    C[(size_t)m * N + n] = acc[i][j][r];
                }
            }
        }
    }
}

__global__ void __launch_bounds__(256, 2) sgemm_qkv(
    const float* __restrict__ A,
    const float* __restrict__ Wq, const float* __restrict__ Wk,
    const float* __restrict__ Wv,
    float* __restrict__ q, float* __restrict__ k, float* __restrict__ v) {
    const float* W = (blockIdx.z == 0) ? Wq : (blockIdx.z == 1) ? Wk : Wv;
    float* C       = (blockIdx.z == 0) ? q  : (blockIdx.z == 1) ? k  : v;
    gemm_bf16_body<0>(A, W, C, HH, HH);
}

__global__ void __launch_bounds__(256, 2) sgemm_out(
    const float* __restrict__ A, const float* __restrict__ W,
    float* __restrict__ C) {
    gemm_bf16_body<1>(A, W, C, HH, HH);
}

// ---------------- RoPE (unchanged, validated) -------------------------------
__global__ void __launch_bounds__(256) rope_kernel(
    float* __restrict__ q, float* __restrict__ k,
    const float* __restrict__ cosp, const float* __restrict__ sinp) {
    const int total = BB * NH * SS * (HD / 2);
    int idx = blockIdx.x * blockDim.x + threadIdx.x;
    float* ptr = q;
    if (idx >= total) { idx -= total; ptr = k; }
    if (idx >= total) return;

    int hd = idx & 63;
    int ro = idx >> 6;
    int s  = ro & (SS - 1);
    size_t base = (size_t)ro * HD;

    float x1 = ptr[base + hd];
    float x2 = ptr[base + hd + 64];
    float c1 = cosp[s * HD + hd];
    float s1 = sinp[s * HD + hd];
    float c2 = cosp[s * HD + hd + 64];
    float s2 = sinp[s * HD + hd + 64];
    ptr[base + hd]      = x1 * c1 - x2 * s1;
    ptr[base + hd + 64] = x2 * c2 + x1 * s2;
}

// ---------------- Tensorized flash attention (validated R15 version) -------
#define BQF 128
#define BKF 64
#define QP  132
#define VP  68
#define PP  68
#define SM_QS 0
#define SM_KS (BQF * QP)
#define SM_VT (SM_KS + BKF * QP)
#define SM_PS (SM_VT + HD * VP)
#define FLASH2_SMEM ((SM_PS + BQF * PP) * 4)

__global__ void __launch_bounds__(256, 1) flash_mma_kernel(
    const float* __restrict__ q, const float* __restrict__ k,
    const float* __restrict__ v, float* __restrict__ out) {
    extern __shared__ float sm[];
    float* Qs = sm + SM_QS;   // [128][132]
    float* Ks = sm + SM_KS;   // [64][132]
    float* Vt = sm + SM_VT;   // [128][68]
    float* Ps = sm + SM_PS;   // [128][68]

    const int qt = (SS / BQF - 1) - blockIdx.x;   // heavy tiles first
    const int nh = blockIdx.y;
    const int b  = blockIdx.z;
    const int bh = b * NH + nh;
    const float* qb = q + (size_t)bh * SS * HD;
    const float* kb = k + (size_t)bh * SS * HD;
    const float* vb = v + (size_t)bh * SS * HD;

    const int tid  = threadIdx.x;
    const int wid  = tid >> 5;
    const int lane = tid & 31;
    const int g  = lane >> 2;
    const int tg = lane & 3;
    const int r0 = wid * 16 + g;
    const int qg0 = qt * BQF + r0;
    const int qg1 = qg0 + 8;

    for (int i = tid; i < BQF * (HD / 4); i += 256) {
        int row = i >> 5, c4 = i & 31;
        *(float4*)&Qs[row * QP + c4 * 4] =
            ((const float4*)(qb + (size_t)(qt * BQF + row) * HD))[c4];
    }

    float o[16][4];
#pragma unroll
    for (int j = 0; j < 16; j++)
#pragma unroll
        for (int r = 0; r < 4; r++) o[j][r] = 0.f;
    float m0 = -INFINITY, m1 = -INFINITY, l0 = 0.f, l1 = 0.f;

    const int nkt = 2 * qt + 2;
    for (int kt = 0; kt < nkt; ++kt) {
        __syncthreads();
        for (int i = tid; i < BKF * (HD / 4); i += 256) {
            int row = i >> 5, c4 = i & 31;
            *(float4*)&Ks[row * QP + c4 * 4] =
                ((const float4*)(kb + (size_t)(kt * BKF + row) * HD))[c4];
            float4 v4 = ((const float4*)(vb + (size_t)(kt * BKF + row) * HD))[c4];
            Vt[(c4 * 4 + 0) * VP + row] = v4.x;
            Vt[(c4 * 4 + 1) * VP + row] = v4.y;
            Vt[(c4 * 4 + 2) * VP + row] = v4.z;
            Vt[(c4 * 4 + 3) * VP + row] = v4.w;
        }
        __syncthreads();

        // ---- S = Q K^T (m16n8k16 chunks) ----
        float s[8][4];
#pragma unroll
        for (int j = 0; j < 8; j++)
#pragma unroll
            for (int r = 0; r < 4; r++) s[j][r] = 0.f;

        for (int k0 = 0; k0 < HD; k0 += 16) {
            uint32_t Ah[4], Al[4];
            float2 fa;
            fa = *(const float2*)&Qs[r0 * QP + k0 + 2 * tg];
            split_bf16x2(fa.x, fa.y, Ah[0], Al[0]);
            fa = *(const float2*)&Qs[(r0 + 8) * QP + k0 + 2 * tg];
            split_bf16x2(fa.x, fa.y, Ah[1], Al[1]);
            fa = *(const float2*)&Qs[r0 * QP + k0 + 2 * tg + 8];
            split_bf16x2(fa.x, fa.y, Ah[2], Al[2]);
            fa = *(const float2*)&Qs[(r0 + 8) * QP + k0 + 2 * tg + 8];
            split_bf16x2(fa.x, fa.y, Ah[3], Al[3]);
#pragma unroll
            for (int nj = 0; nj < 8; nj++) {
                uint32_t Bh[2], Bl[2];
                float2 fb;
                fb = *(const float2*)&Ks[(nj * 8 + g) * QP + k0 + 2 * tg];
                split_bf16x2(fb.x, fb.y, Bh[0], Bl[0]);
                fb = *(const float2*)&Ks[(nj * 8 + g) * QP + k0 + 2 * tg + 8];
                split_bf16x2(fb.x, fb.y, Bh[1], Bl[1]);
                mma_bf16(s[nj], Ah, Bh);
                mma_bf16(s[nj], Ah, Bl);
                mma_bf16(s[nj], Al, Bh);
            }
        }

        // ---- online softmax (unchanged) ----
        const int colbase = kt * BKF + tg * 2;
        float rm0 = -INFINITY, rm1 = -INFINITY;
#pragma unroll
        for (int nj = 0; nj < 8; nj++) {
#pragma unroll
            for (int e = 0; e < 2; e++) {
                int c = colbase + nj * 8 + e;
                float v0 = s[nj][e] * SCALE;
                if (c > qg0) v0 = -INFINITY;
                s[nj][e] = v0;
                rm0 = fmaxf(rm0, v0);
                float v1 = s[nj][2 + e] * SCALE;
                if (c > qg1) v1 = -INFINITY;
                s[nj][2 + e] = v1;
                rm1 = fmaxf(rm1, v1);
            }
        }
        rm0 = fmaxf(rm0, __shfl_xor_sync(0xffffffffu, rm0, 1));
        rm0 = fmaxf(rm0, __shfl_xor_sync(0xffffffffu, rm0, 2));
        rm1 = fmaxf(rm1, __shfl_xor_sync(0xffffffffu, rm1, 1));
        rm1 = fmaxf(rm1, __shfl_xor_sync(0xffffffffu, rm1, 2));

        float mn0 = fmaxf(m0, rm0), mn1 = fmaxf(m1, rm1);
        float cr0 = __expf(m0 - mn0), cr1 = __expf(m1 - mn1);
        float rs0 = 0.f, rs1 = 0.f;
#pragma unroll
        for (int nj = 0; nj < 8; nj++) {
            float p0 = __expf(s[nj][0] - mn0);
            float p1 = __expf(s[nj][1] - mn0);
            float p2 = __expf(s[nj][2] - mn1);
            float p3 = __expf(s[nj][3] - mn1);
            rs0 += p0 + p1;
            rs1 += p2 + p3;
            *(float2*)&Ps[r0 * PP + nj * 8 + 2 * tg]       = make_float2(p0, p1);
            *(float2*)&Ps[(r0 + 8) * PP + nj * 8 + 2 * tg] = make_float2(p2, p3);
        }
        rs0 += __shfl_xor_sync(0xffffffffu, rs0, 1);
        rs0 += __shfl_xor_sync(0xffffffffu, rs0, 2);
        rs1 += __shfl_xor_sync(0xffffffffu, rs1, 1);
        rs1 += __shfl_xor_sync(0xffffffffu, rs1, 2);
        l0 = l0 * cr0 + rs0;
        l1 = l1 * cr1 + rs1;
        m0 = mn0; m1 = mn1;
#pragma unroll
        for (int j = 0; j < 16; j++) {
            o[j][0] *= cr0; o[j][1] *= cr0;
            o[j][2] *= cr1; o[j][3] *= cr1;
        }
        __syncwarp();   // Ps rows warp-private; publish cross-lane writes

        // ---- O += P V (m16n8k16 chunks) ----
        for (int k0 = 0; k0 < BKF; k0 += 16) {
            uint32_t Ah[4], Al[4];
            float2 fa;
            fa = *(const float2*)&Ps[r0 * PP + k0 + 2 * tg];
            split_bf16x2(fa.x, fa.y, Ah[0], Al[0]);
            fa = *(const float2*)&Ps[(r0 + 8) * PP + k0 + 2 * tg];
            split_bf16x2(fa.x, fa.y, Ah[1], Al[1]);
            fa = *(const float2*)&Ps[r0 * PP + k0 + 2 * tg + 8];
            split_bf16x2(fa.x, fa.y, Ah[2], Al[2]);
            fa = *(const float2*)&Ps[(r0 + 8) * PP + k0 + 2 * tg + 8];
            split_bf16x2(fa.x, fa.y, Ah[3], Al[3]);
#pragma unroll
            for (int nj = 0; nj < 16; nj++) {
                uint32_t Bh[2], Bl[2];
                float2 fb;
                fb = *(const float2*)&Vt[(nj * 8 + g) * VP + k0 + 2 * tg];
                split_bf16x2(fb.x, fb.y, Bh[0], Bl[0]);
                fb = *(const float2*)&Vt[(nj * 8 + g) * VP + k0 + 2 * tg + 8];
                split_bf16x2(fb.x, fb.y, Bh[1], Bl[1]);
                mma_bf16(o[nj], Ah, Bh);
                mma_bf16(o[nj], Ah, Bl);
                mma_bf16(o[nj], Al, Bh);
            }
        }
    }

    float il0 = 1.0f / l0, il1 = 1.0f / l1;
    float* ob0 = out + ((size_t)(b * SS + qg0)) * HH + nh * HD;
    float* ob1 = out + ((size_t)(b * SS + qg1)) * HH + nh * HD;
#pragma unroll
    for (int nj = 0; nj < 16; nj++) {
        *(float2*)&ob0[nj * 8 + 2 * tg] = make_float2(o[nj][0] * il0, o[nj][1] * il0);
        *(float2*)&ob1[nj * 8 + 2 * tg] = make_float2(o[nj][2] * il1, o[nj][3] * il1);
    }
}

// ---------------- launch ---------------------------------------------------
extern "C" void kernel_launch(void* const* d_in, const int* in_sizes, int n_in,
                              void* d_out, int out_size) {
    const float* hs   = (const float*)d_in[0];
    const float* cosp = (const float*)d_in[1];
    const float* sinp = (const float*)d_in[2];
    const float* Wq   = (const float*)d_in[3];
    const float* Wk   = (const float*)d_in[4];
    const float* Wv   = (const float*)d_in[5];
    const float* Wo   = (const float*)d_in[6];
    float* out = (float*)d_out;

    float *qp, *kp, *vp, *ap;
    cudaGetSymbolAddress((void**)&qp, g_q);
    cudaGetSymbolAddress((void**)&kp, g_k);
    cudaGetSymbolAddress((void**)&vp, g_v);
    cudaGetSymbolAddress((void**)&ap, g_att);

    cudaFuncSetAttribute(sgemm_qkv,
                         cudaFuncAttributeMaxDynamicSharedMemorySize, GEMM_SMEM_B);
    cudaFuncSetAttribute(sgemm_out,
                         cudaFuncAttributeMaxDynamicSharedMemorySize, GEMM_SMEM_B);
    cudaFuncSetAttribute(flash_mma_kernel,
                         cudaFuncAttributeMaxDynamicSharedMemorySize, FLASH2_SMEM);

    // 1) QKV projections (fused over grid.z)
    dim3 pg(HH / 128, (BB * SS) / 128, 3);
    sgemm_qkv<<<pg, 256, GEMM_SMEM_B>>>(hs, Wq, Wk, Wv, qp, kp, vp);

    // 2) RoPE on q and k
    int pairs = 2 * BB * NH * SS * (HD / 2);
    rope_kernel<<<(pairs + 255) / 256, 256>>>(qp, kp, cosp, sinp);

    // 3) causal flash attention (bf16 k16 tensor cores)
    dim3 fg(SS / BQF, NH, BB);
    flash_mma_kernel<<<fg, 256, FLASH2_SMEM>>>(qp, kp, vp, ap);

    // 4) output projection
    dim3 og(HH / 128, (BB * SS) / 128, 1);
    sgemm_out<<<og, 256, GEMM_SMEM_B>>>(ap, Wo, out);
}